// round 1
// baseline (speedup 1.0000x reference)
#include <cuda_runtime.h>
#include <cstdint>

#define HID 256
#define H4  64            // HID/4 float4 per row
#define NB  1024          // number of graphs
#define EPS 1e-5f

// scratch (allocation-free rule: static __device__ globals)
__device__ float g_hpool[NB * HID];
__device__ float g_h1[NB * HID];
__device__ float g_scale[HID];
__device__ float g_shift[HID];

// ---------------------------------------------------------------------------
// 1) segment-sum pooling (+ virtual_node). batch_idx is SORTED -> binary search
//    per graph, no atomics. 1024 blocks x 256 threads.
//    Thread layout: 64 float4 lanes x 4 row-groups.
// ---------------------------------------------------------------------------
__global__ __launch_bounds__(256) void pool_kernel(
    const float* __restrict__ x, const int* __restrict__ bidx,
    const float* __restrict__ vnode, float* __restrict__ hpool, int n)
{
    int b = blockIdx.x;
    // lower_bound(bidx, b)
    int lo = 0, hi = n;
    while (lo < hi) { int m = (lo + hi) >> 1; if (bidx[m] < b) lo = m + 1; else hi = m; }
    int seg_lo = lo;
    // lower_bound(bidx, b+1)
    hi = n;
    while (lo < hi) { int m = (lo + hi) >> 1; if (bidx[m] < b + 1) lo = m + 1; else hi = m; }
    int seg_hi = lo;

    int t  = threadIdx.x;
    int c4 = t & 63;        // float4 column
    int rg = t >> 6;        // row group 0..3

    const float4* x4 = reinterpret_cast<const float4*>(x);
    float4 acc = make_float4(0.f, 0.f, 0.f, 0.f);
    for (int r = seg_lo + rg; r < seg_hi; r += 4) {
        float4 v = x4[(size_t)r * H4 + c4];
        acc.x += v.x; acc.y += v.y; acc.z += v.z; acc.w += v.w;
    }

    __shared__ float4 sm[256];
    sm[t] = acc;
    __syncthreads();
    if (rg == 0) {
        float4 a = sm[c4], b2 = sm[64 + c4], c = sm[128 + c4], d = sm[192 + c4];
        float4 vn = reinterpret_cast<const float4*>(vnode)[b * H4 + c4];
        float4 o;
        o.x = a.x + b2.x + c.x + d.x + vn.x;
        o.y = a.y + b2.y + c.y + d.y + vn.y;
        o.z = a.z + b2.z + c.z + d.z + vn.z;
        o.w = a.w + b2.w + c.w + d.w + vn.w;
        reinterpret_cast<float4*>(hpool)[b * H4 + c4] = o;
    }
}

// ---------------------------------------------------------------------------
// 2) GEMM1: h1[1024,256] = hpool @ W1 + b1
//    64x64 block tile, 16x16 threads, 4x4 micro-tile, K-tile 16.
// ---------------------------------------------------------------------------
__global__ __launch_bounds__(256) void gemm1_kernel(
    const float* __restrict__ A, const float* __restrict__ W,
    const float* __restrict__ bias, float* __restrict__ C)
{
    __shared__ float  As[64][17];
    __shared__ float4 Bs4[16][16];

    int t  = threadIdx.x;
    int tx = t & 15, ty = t >> 4;
    int m0 = blockIdx.y * 64;
    int n0 = blockIdx.x * 64;

    float acc[4][4];
#pragma unroll
    for (int i = 0; i < 4; i++)
#pragma unroll
        for (int j = 0; j < 4; j++) acc[i][j] = 0.f;

    int arow = t >> 2, aq = t & 3;     // A load: 64 rows x 4 float4-quads
    int brow = t >> 4, bc = t & 15;    // B load: 16 rows x 16 float4 cols

    for (int k0 = 0; k0 < HID; k0 += 16) {
        float4 av = reinterpret_cast<const float4*>(A)[((size_t)(m0 + arow) * HID + k0 + aq * 4) >> 2];
        As[arow][aq * 4 + 0] = av.x;
        As[arow][aq * 4 + 1] = av.y;
        As[arow][aq * 4 + 2] = av.z;
        As[arow][aq * 4 + 3] = av.w;
        Bs4[brow][bc] = reinterpret_cast<const float4*>(W)[((size_t)(k0 + brow) * HID + n0 + bc * 4) >> 2];
        __syncthreads();
#pragma unroll
        for (int kk = 0; kk < 16; kk++) {
            float4 bb = Bs4[kk][tx];
            float a0 = As[ty * 4 + 0][kk];
            float a1 = As[ty * 4 + 1][kk];
            float a2 = As[ty * 4 + 2][kk];
            float a3 = As[ty * 4 + 3][kk];
            acc[0][0] += a0 * bb.x; acc[0][1] += a0 * bb.y; acc[0][2] += a0 * bb.z; acc[0][3] += a0 * bb.w;
            acc[1][0] += a1 * bb.x; acc[1][1] += a1 * bb.y; acc[1][2] += a1 * bb.z; acc[1][3] += a1 * bb.w;
            acc[2][0] += a2 * bb.x; acc[2][1] += a2 * bb.y; acc[2][2] += a2 * bb.z; acc[2][3] += a2 * bb.w;
            acc[3][0] += a3 * bb.x; acc[3][1] += a3 * bb.y; acc[3][2] += a3 * bb.z; acc[3][3] += a3 * bb.w;
        }
        __syncthreads();
    }

    float4 bv = reinterpret_cast<const float4*>(bias)[(n0 >> 2) + tx];
#pragma unroll
    for (int i = 0; i < 4; i++) {
        float4 o;
        o.x = acc[i][0] + bv.x; o.y = acc[i][1] + bv.y;
        o.z = acc[i][2] + bv.z; o.w = acc[i][3] + bv.w;
        reinterpret_cast<float4*>(C)[((size_t)(m0 + ty * 4 + i) * HID + n0 + tx * 4) >> 2] = o;
    }
}

// ---------------------------------------------------------------------------
// 3) per-channel batchnorm stats -> scale/shift. 256 blocks (one per channel).
// ---------------------------------------------------------------------------
__global__ __launch_bounds__(256) void stats_kernel(
    const float* __restrict__ h1, const float* __restrict__ gamma,
    const float* __restrict__ beta, float* __restrict__ scale,
    float* __restrict__ shift)
{
    int j = blockIdx.x, t = threadIdx.x;
    float s = 0.f, q = 0.f;
#pragma unroll
    for (int r = t; r < NB; r += 256) {
        float v = h1[(size_t)r * HID + j];
        s += v; q += v * v;
    }
#pragma unroll
    for (int o = 16; o > 0; o >>= 1) {
        s += __shfl_down_sync(0xffffffffu, s, o);
        q += __shfl_down_sync(0xffffffffu, q, o);
    }
    __shared__ float ss[8], qq[8];
    if ((t & 31) == 0) { ss[t >> 5] = s; qq[t >> 5] = q; }
    __syncthreads();
    if (t == 0) {
        float S = 0.f, Q = 0.f;
#pragma unroll
        for (int w = 0; w < 8; w++) { S += ss[w]; Q += qq[w]; }
        float mean = S * (1.f / NB);
        float var  = Q * (1.f / NB) - mean * mean;
        float sc   = gamma[j] * rsqrtf(var + EPS);
        scale[j] = sc;
        shift[j] = beta[j] - mean * sc;
    }
}

// ---------------------------------------------------------------------------
// 4) GEMM2 with fused BN-normalize + ReLU on the A operand:
//    vn = relu(h1*scale + shift) @ W2 + b2
// ---------------------------------------------------------------------------
__global__ __launch_bounds__(256) void gemm2_kernel(
    const float* __restrict__ A, const float* __restrict__ W,
    const float* __restrict__ bias, const float* __restrict__ scale,
    const float* __restrict__ shift, float* __restrict__ C)
{
    __shared__ float  As[64][17];
    __shared__ float4 Bs4[16][16];

    int t  = threadIdx.x;
    int tx = t & 15, ty = t >> 4;
    int m0 = blockIdx.y * 64;
    int n0 = blockIdx.x * 64;

    float acc[4][4];
#pragma unroll
    for (int i = 0; i < 4; i++)
#pragma unroll
        for (int j = 0; j < 4; j++) acc[i][j] = 0.f;

    int arow = t >> 2, aq = t & 3;
    int brow = t >> 4, bc = t & 15;

    for (int k0 = 0; k0 < HID; k0 += 16) {
        int kc = k0 + aq * 4;
        float4 av = reinterpret_cast<const float4*>(A)[((size_t)(m0 + arow) * HID + kc) >> 2];
        float4 sc = reinterpret_cast<const float4*>(scale)[kc >> 2];
        float4 sh = reinterpret_cast<const float4*>(shift)[kc >> 2];
        As[arow][aq * 4 + 0] = fmaxf(av.x * sc.x + sh.x, 0.f);
        As[arow][aq * 4 + 1] = fmaxf(av.y * sc.y + sh.y, 0.f);
        As[arow][aq * 4 + 2] = fmaxf(av.z * sc.z + sh.z, 0.f);
        As[arow][aq * 4 + 3] = fmaxf(av.w * sc.w + sh.w, 0.f);
        Bs4[brow][bc] = reinterpret_cast<const float4*>(W)[((size_t)(k0 + brow) * HID + n0 + bc * 4) >> 2];
        __syncthreads();
#pragma unroll
        for (int kk = 0; kk < 16; kk++) {
            float4 bb = Bs4[kk][tx];
            float a0 = As[ty * 4 + 0][kk];
            float a1 = As[ty * 4 + 1][kk];
            float a2 = As[ty * 4 + 2][kk];
            float a3 = As[ty * 4 + 3][kk];
            acc[0][0] += a0 * bb.x; acc[0][1] += a0 * bb.y; acc[0][2] += a0 * bb.z; acc[0][3] += a0 * bb.w;
            acc[1][0] += a1 * bb.x; acc[1][1] += a1 * bb.y; acc[1][2] += a1 * bb.z; acc[1][3] += a1 * bb.w;
            acc[2][0] += a2 * bb.x; acc[2][1] += a2 * bb.y; acc[2][2] += a2 * bb.z; acc[2][3] += a2 * bb.w;
            acc[3][0] += a3 * bb.x; acc[3][1] += a3 * bb.y; acc[3][2] += a3 * bb.z; acc[3][3] += a3 * bb.w;
        }
        __syncthreads();
    }

    float4 bv = reinterpret_cast<const float4*>(bias)[(n0 >> 2) + tx];
#pragma unroll
    for (int i = 0; i < 4; i++) {
        float4 o;
        o.x = acc[i][0] + bv.x; o.y = acc[i][1] + bv.y;
        o.z = acc[i][2] + bv.z; o.w = acc[i][3] + bv.w;
        reinterpret_cast<float4*>(C)[((size_t)(m0 + ty * 4 + i) * HID + n0 + tx * 4) >> 2] = o;
    }
}

// ---------------------------------------------------------------------------
// 5) gather broadcast-add: x_out = x + vn[batch_idx].  float4 grid; vn (1 MB)
//    is L2-resident, batch_idx load is warp-uniform.
// ---------------------------------------------------------------------------
__global__ __launch_bounds__(256) void gather_kernel(
    const float* __restrict__ x, const int* __restrict__ bidx,
    const float* __restrict__ vn, float* __restrict__ out, long total4)
{
    long i = (long)blockIdx.x * blockDim.x + threadIdx.x;
    if (i >= total4) return;
    int r = (int)(i >> 6);
    int c = (int)(i & 63);
    int g = __ldg(&bidx[r]);
    float4 a = reinterpret_cast<const float4*>(x)[i];
    float4 v = reinterpret_cast<const float4*>(vn)[(size_t)g * H4 + c];
    float4 o;
    o.x = a.x + v.x; o.y = a.y + v.y; o.z = a.z + v.z; o.w = a.w + v.w;
    reinterpret_cast<float4*>(out)[i] = o;
}

// ---------------------------------------------------------------------------
extern "C" void kernel_launch(void* const* d_in, const int* in_sizes, int n_in,
                              void* d_out, int out_size)
{
    const float* x     = (const float*)d_in[0];
    const int*   bidx  = (const int*)  d_in[1];
    const float* vnode = (const float*)d_in[2];
    const float* W1    = (const float*)d_in[3];
    const float* b1    = (const float*)d_in[4];
    const float* gamma = (const float*)d_in[5];
    const float* beta  = (const float*)d_in[6];
    const float* W2    = (const float*)d_in[7];
    const float* b2    = (const float*)d_in[8];

    int n = in_sizes[0] / HID;          // number of nodes

    float* out   = (float*)d_out;       // x_out: [n, H]
    float* vnout = out + (size_t)n * HID;  // vn: [B, H] (tuple order)

    float* hpool; cudaGetSymbolAddress((void**)&hpool, g_hpool);
    float* h1;    cudaGetSymbolAddress((void**)&h1,    g_h1);
    float* scale; cudaGetSymbolAddress((void**)&scale, g_scale);
    float* shift; cudaGetSymbolAddress((void**)&shift, g_shift);

    pool_kernel<<<NB, 256>>>(x, bidx, vnode, hpool, n);

    dim3 ggrid(HID / 64, NB / 64);      // (4, 16)
    gemm1_kernel<<<ggrid, 256>>>(hpool, W1, b1, h1);

    stats_kernel<<<HID, 256>>>(h1, gamma, beta, scale, shift);

    gemm2_kernel<<<ggrid, 256>>>(h1, W2, b2, scale, shift, vnout);

    long total4 = (long)n * H4;
    int blocks = (int)((total4 + 255) / 256);
    gather_kernel<<<blocks, 256>>>(x, bidx, vnout, out, total4);
}

// round 2
// speedup vs baseline: 1.1781x; 1.1781x over previous
#include <cuda_runtime.h>
#include <cstdint>

#define HID 256
#define H4  64            // HID/4 float4 per row
#define NB  1024          // number of graphs
#define EPS 1e-5f

// scratch (allocation-free rule: static __device__ globals)
__device__ float g_hpool[NB * HID];
__device__ float g_h1[NB * HID];
__device__ float g_sum[HID];
__device__ float g_sumsq[HID];

// ---------------------------------------------------------------------------
// 1) segment-sum pooling (+ virtual_node). batch_idx SORTED -> binary search.
//    2 blocks per graph (column halves). 256 thr = 32 float4 cols x 8 rowgrps.
//    Block 0 also zeroes the BN stat accumulators for this iteration.
// ---------------------------------------------------------------------------
__global__ __launch_bounds__(256) void pool_kernel(
    const float* __restrict__ x, const int* __restrict__ bidx,
    const float* __restrict__ vnode, float* __restrict__ hpool,
    float* __restrict__ gsum, float* __restrict__ gsumsq, int n)
{
    int t = threadIdx.x;
    if (blockIdx.x == 0) { gsum[t] = 0.f; gsumsq[t] = 0.f; }

    int b    = blockIdx.x >> 1;
    int half = blockIdx.x & 1;

    // lower_bound(bidx, b)
    int lo = 0, hi = n;
    while (lo < hi) { int m = (lo + hi) >> 1; if (bidx[m] < b) lo = m + 1; else hi = m; }
    int seg_lo = lo;
    // lower_bound(bidx, b+1)
    hi = n;
    while (lo < hi) { int m = (lo + hi) >> 1; if (bidx[m] < b + 1) lo = m + 1; else hi = m; }
    int seg_hi = lo;

    int c4 = (half << 5) + (t & 31);   // global float4 column 0..63
    int rg = t >> 5;                   // row group 0..7

    const float4* x4 = reinterpret_cast<const float4*>(x);
    float4 acc = make_float4(0.f, 0.f, 0.f, 0.f);
    for (int r = seg_lo + rg; r < seg_hi; r += 8) {
        float4 v = __ldcs(&x4[(size_t)r * H4 + c4]);
        acc.x += v.x; acc.y += v.y; acc.z += v.z; acc.w += v.w;
    }

    __shared__ float4 sm[256];
    sm[t] = acc;
    __syncthreads();
    if (t < 32) {
        float4 o = reinterpret_cast<const float4*>(vnode)[b * H4 + c4];
#pragma unroll
        for (int g = 0; g < 8; g++) {
            float4 v = sm[g * 32 + t];
            o.x += v.x; o.y += v.y; o.z += v.z; o.w += v.w;
        }
        reinterpret_cast<float4*>(hpool)[b * H4 + c4] = o;
    }
}

// ---------------------------------------------------------------------------
// 2) GEMM1: h1 = hpool @ W1 + b1, fused BN-stat partial sums (atomicAdd).
//    32x64 tile, K-chunk 32, 256 thr, 2x4 micro-tile. grid (4,32)=128 blocks.
// ---------------------------------------------------------------------------
__global__ __launch_bounds__(256) void gemm1_kernel(
    const float* __restrict__ A, const float* __restrict__ W,
    const float* __restrict__ bias, float* __restrict__ C,
    float* __restrict__ gsum, float* __restrict__ gsumsq)
{
    __shared__ float  As[32][33];
    __shared__ float4 Bs4[32][16];
    __shared__ float  red_s[16][64];
    __shared__ float  red_q[16][64];

    int t  = threadIdx.x;
    int tx = t & 15, ty = t >> 4;
    int m0 = blockIdx.y * 32;
    int n0 = blockIdx.x * 64;

    float acc[2][4];
#pragma unroll
    for (int i = 0; i < 2; i++)
#pragma unroll
        for (int j = 0; j < 4; j++) acc[i][j] = 0.f;

    int arow = t >> 3, aq = t & 7;     // A: 32 rows x 8 float4
    int brow = t >> 4, bq = t & 15;    // B: 16 rows x 16 float4 (x2)

    for (int k0 = 0; k0 < HID; k0 += 32) {
        float4 av = *reinterpret_cast<const float4*>(&A[(size_t)(m0 + arow) * HID + k0 + aq * 4]);
        As[arow][aq * 4 + 0] = av.x;
        As[arow][aq * 4 + 1] = av.y;
        As[arow][aq * 4 + 2] = av.z;
        As[arow][aq * 4 + 3] = av.w;
        Bs4[brow][bq]      = *reinterpret_cast<const float4*>(&W[(size_t)(k0 + brow) * HID + n0 + bq * 4]);
        Bs4[brow + 16][bq] = *reinterpret_cast<const float4*>(&W[(size_t)(k0 + brow + 16) * HID + n0 + bq * 4]);
        __syncthreads();
#pragma unroll
        for (int kk = 0; kk < 32; kk++) {
            float4 bb = Bs4[kk][tx];
            float a0 = As[ty * 2 + 0][kk];
            float a1 = As[ty * 2 + 1][kk];
            acc[0][0] += a0 * bb.x; acc[0][1] += a0 * bb.y; acc[0][2] += a0 * bb.z; acc[0][3] += a0 * bb.w;
            acc[1][0] += a1 * bb.x; acc[1][1] += a1 * bb.y; acc[1][2] += a1 * bb.z; acc[1][3] += a1 * bb.w;
        }
        __syncthreads();
    }

    float4 bv = *reinterpret_cast<const float4*>(&bias[n0 + tx * 4]);
    float v0[4], v1[4];
    v0[0] = acc[0][0] + bv.x; v0[1] = acc[0][1] + bv.y; v0[2] = acc[0][2] + bv.z; v0[3] = acc[0][3] + bv.w;
    v1[0] = acc[1][0] + bv.x; v1[1] = acc[1][1] + bv.y; v1[2] = acc[1][2] + bv.z; v1[3] = acc[1][3] + bv.w;

    float4 o0 = make_float4(v0[0], v0[1], v0[2], v0[3]);
    float4 o1 = make_float4(v1[0], v1[1], v1[2], v1[3]);
    *reinterpret_cast<float4*>(&C[(size_t)(m0 + ty * 2 + 0) * HID + n0 + tx * 4]) = o0;
    *reinterpret_cast<float4*>(&C[(size_t)(m0 + ty * 2 + 1) * HID + n0 + tx * 4]) = o1;

#pragma unroll
    for (int j = 0; j < 4; j++) {
        red_s[ty][tx * 4 + j] = v0[j] + v1[j];
        red_q[ty][tx * 4 + j] = v0[j] * v0[j] + v1[j] * v1[j];
    }
    __syncthreads();
    if (t < 64) {
        float S = 0.f, Q = 0.f;
#pragma unroll
        for (int g = 0; g < 16; g++) { S += red_s[g][t]; Q += red_q[g][t]; }
        atomicAdd(&gsum[n0 + t],   S);
        atomicAdd(&gsumsq[n0 + t], Q);
    }
}

// ---------------------------------------------------------------------------
// 3) GEMM2: vn = relu(h1*scale + shift) @ W2 + b2.
//    Prologue computes scale/shift per channel from gsum/gsumsq in smem.
// ---------------------------------------------------------------------------
__global__ __launch_bounds__(256) void gemm2_kernel(
    const float* __restrict__ A, const float* __restrict__ W,
    const float* __restrict__ bias, const float* __restrict__ gamma,
    const float* __restrict__ beta, const float* __restrict__ gsum,
    const float* __restrict__ gsumsq, float* __restrict__ C)
{
    __shared__ float  As[32][33];
    __shared__ float4 Bs4[32][16];
    __shared__ float  scale_s[HID];
    __shared__ float  shift_s[HID];

    int t  = threadIdx.x;
    {
        float mean = gsum[t] * (1.f / NB);
        float var  = gsumsq[t] * (1.f / NB) - mean * mean;
        float sc   = gamma[t] * rsqrtf(var + EPS);
        scale_s[t] = sc;
        shift_s[t] = beta[t] - mean * sc;
    }
    __syncthreads();

    int tx = t & 15, ty = t >> 4;
    int m0 = blockIdx.y * 32;
    int n0 = blockIdx.x * 64;

    float acc[2][4];
#pragma unroll
    for (int i = 0; i < 2; i++)
#pragma unroll
        for (int j = 0; j < 4; j++) acc[i][j] = 0.f;

    int arow = t >> 3, aq = t & 7;
    int brow = t >> 4, bq = t & 15;

    for (int k0 = 0; k0 < HID; k0 += 32) {
        int kc = k0 + aq * 4;
        float4 av = *reinterpret_cast<const float4*>(&A[(size_t)(m0 + arow) * HID + kc]);
        As[arow][aq * 4 + 0] = fmaxf(av.x * scale_s[kc + 0] + shift_s[kc + 0], 0.f);
        As[arow][aq * 4 + 1] = fmaxf(av.y * scale_s[kc + 1] + shift_s[kc + 1], 0.f);
        As[arow][aq * 4 + 2] = fmaxf(av.z * scale_s[kc + 2] + shift_s[kc + 2], 0.f);
        As[arow][aq * 4 + 3] = fmaxf(av.w * scale_s[kc + 3] + shift_s[kc + 3], 0.f);
        Bs4[brow][bq]      = *reinterpret_cast<const float4*>(&W[(size_t)(k0 + brow) * HID + n0 + bq * 4]);
        Bs4[brow + 16][bq] = *reinterpret_cast<const float4*>(&W[(size_t)(k0 + brow + 16) * HID + n0 + bq * 4]);
        __syncthreads();
#pragma unroll
        for (int kk = 0; kk < 32; kk++) {
            float4 bb = Bs4[kk][tx];
            float a0 = As[ty * 2 + 0][kk];
            float a1 = As[ty * 2 + 1][kk];
            acc[0][0] += a0 * bb.x; acc[0][1] += a0 * bb.y; acc[0][2] += a0 * bb.z; acc[0][3] += a0 * bb.w;
            acc[1][0] += a1 * bb.x; acc[1][1] += a1 * bb.y; acc[1][2] += a1 * bb.z; acc[1][3] += a1 * bb.w;
        }
        __syncthreads();
    }

    float4 bv = *reinterpret_cast<const float4*>(&bias[n0 + tx * 4]);
#pragma unroll
    for (int i = 0; i < 2; i++) {
        float4 o;
        o.x = acc[i][0] + bv.x; o.y = acc[i][1] + bv.y;
        o.z = acc[i][2] + bv.z; o.w = acc[i][3] + bv.w;
        *reinterpret_cast<float4*>(&C[(size_t)(m0 + ty * 2 + i) * HID + n0 + tx * 4]) = o;
    }
}

// ---------------------------------------------------------------------------
// 4) gather broadcast-add: x_out = x + vn[batch_idx].
//    x streamed (ldcs), out streamed (stcs) so vn/bidx stay L2-resident.
// ---------------------------------------------------------------------------
__global__ __launch_bounds__(256) void gather_kernel(
    const float* __restrict__ x, const int* __restrict__ bidx,
    const float* __restrict__ vn, float* __restrict__ out, long total4)
{
    long i = (long)blockIdx.x * blockDim.x + threadIdx.x;
    if (i >= total4) return;
    int r = (int)(i >> 6);
    int c = (int)(i & 63);
    int g = __ldg(&bidx[r]);
    float4 a = __ldcs(&reinterpret_cast<const float4*>(x)[i]);
    float4 v = reinterpret_cast<const float4*>(vn)[(size_t)g * H4 + c];
    float4 o;
    o.x = a.x + v.x; o.y = a.y + v.y; o.z = a.z + v.z; o.w = a.w + v.w;
    __stcs(&reinterpret_cast<float4*>(out)[i], o);
}

// ---------------------------------------------------------------------------
extern "C" void kernel_launch(void* const* d_in, const int* in_sizes, int n_in,
                              void* d_out, int out_size)
{
    const float* x     = (const float*)d_in[0];
    const int*   bidx  = (const int*)  d_in[1];
    const float* vnode = (const float*)d_in[2];
    const float* W1    = (const float*)d_in[3];
    const float* b1    = (const float*)d_in[4];
    const float* gamma = (const float*)d_in[5];
    const float* beta  = (const float*)d_in[6];
    const float* W2    = (const float*)d_in[7];
    const float* b2    = (const float*)d_in[8];

    int n = in_sizes[0] / HID;             // number of nodes

    float* out   = (float*)d_out;          // x_out: [n, H]
    float* vnout = out + (size_t)n * HID;  // vn: [B, H]

    float* hpool; cudaGetSymbolAddress((void**)&hpool, g_hpool);
    float* h1;    cudaGetSymbolAddress((void**)&h1,    g_h1);
    float* gsum;  cudaGetSymbolAddress((void**)&gsum,  g_sum);
    float* gsq;   cudaGetSymbolAddress((void**)&gsq,   g_sumsq);

    pool_kernel<<<NB * 2, 256>>>(x, bidx, vnode, hpool, gsum, gsq, n);

    dim3 ggrid(HID / 64, NB / 32);         // (4, 32) = 128 blocks
    gemm1_kernel<<<ggrid, 256>>>(hpool, W1, b1, h1, gsum, gsq);
    gemm2_kernel<<<ggrid, 256>>>(h1, W2, b2, gamma, beta, gsum, gsq, vnout);

    long total4 = (long)n * H4;
    int blocks = (int)((total4 + 255) / 256);
    gather_kernel<<<blocks, 256>>>(x, bidx, vnout, out, total4);
}

// round 3
// speedup vs baseline: 1.2145x; 1.0309x over previous
#include <cuda_runtime.h>
#include <cstdint>

#define HID 256
#define H4  64            // HID/4 float4 per row
#define NB  1024          // number of graphs
#define EPS 1e-5f

// scratch (allocation-free rule: static __device__ globals)
__device__ float g_hpool[NB * HID];
__device__ float g_h1[NB * HID];
__device__ float g_sum[HID];
__device__ float g_sumsq[HID];

// ---------------------------------------------------------------------------
// 1) segment-sum pooling (+ virtual_node). batch_idx SORTED -> binary search.
//    2 blocks per graph (column halves). 256 thr = 32 float4 cols x 8 rowgrps.
//    Block 0 also zeroes the BN stat accumulators for this iteration.
// ---------------------------------------------------------------------------
__global__ __launch_bounds__(256) void pool_kernel(
    const float* __restrict__ x, const int* __restrict__ bidx,
    const float* __restrict__ vnode, float* __restrict__ hpool,
    float* __restrict__ gsum, float* __restrict__ gsumsq, int n)
{
    int t = threadIdx.x;
    if (blockIdx.x == 0) { gsum[t] = 0.f; gsumsq[t] = 0.f; }

    int b    = blockIdx.x >> 1;
    int half = blockIdx.x & 1;

    // lower_bound(bidx, b)
    int lo = 0, hi = n;
    while (lo < hi) { int m = (lo + hi) >> 1; if (bidx[m] < b) lo = m + 1; else hi = m; }
    int seg_lo = lo;
    // lower_bound(bidx, b+1)
    hi = n;
    while (lo < hi) { int m = (lo + hi) >> 1; if (bidx[m] < b + 1) lo = m + 1; else hi = m; }
    int seg_hi = lo;

    int c4 = (half << 5) + (t & 31);   // global float4 column 0..63
    int rg = t >> 5;                   // row group 0..7

    const float4* x4 = reinterpret_cast<const float4*>(x);
    float4 acc = make_float4(0.f, 0.f, 0.f, 0.f);
#pragma unroll 4
    for (int r = seg_lo + rg; r < seg_hi; r += 8) {
        float4 v = __ldcs(&x4[(size_t)r * H4 + c4]);
        acc.x += v.x; acc.y += v.y; acc.z += v.z; acc.w += v.w;
    }

    __shared__ float4 sm[256];
    sm[t] = acc;
    __syncthreads();
    if (t < 32) {
        float4 o = reinterpret_cast<const float4*>(vnode)[b * H4 + c4];
#pragma unroll
        for (int g = 0; g < 8; g++) {
            float4 v = sm[g * 32 + t];
            o.x += v.x; o.y += v.y; o.z += v.z; o.w += v.w;
        }
        reinterpret_cast<float4*>(hpool)[b * H4 + c4] = o;
    }
}

// ---------------------------------------------------------------------------
// 2) GEMM1: h1 = hpool @ W1 + b1, fused BN-stat partial sums (atomicAdd).
//    32x64 tile, K-chunk 32, 256 thr, 2x4 micro-tile. grid (4,32)=128 blocks.
// ---------------------------------------------------------------------------
__global__ __launch_bounds__(256) void gemm1_kernel(
    const float* __restrict__ A, const float* __restrict__ W,
    const float* __restrict__ bias, float* __restrict__ C,
    float* __restrict__ gsum, float* __restrict__ gsumsq)
{
    __shared__ float  As[32][33];
    __shared__ float4 Bs4[32][16];
    __shared__ float  red_s[16][64];
    __shared__ float  red_q[16][64];

    int t  = threadIdx.x;
    int tx = t & 15, ty = t >> 4;
    int m0 = blockIdx.y * 32;
    int n0 = blockIdx.x * 64;

    float acc[2][4];
#pragma unroll
    for (int i = 0; i < 2; i++)
#pragma unroll
        for (int j = 0; j < 4; j++) acc[i][j] = 0.f;

    int arow = t >> 3, aq = t & 7;     // A: 32 rows x 8 float4
    int brow = t >> 4, bq = t & 15;    // B: 16 rows x 16 float4 (x2)

    for (int k0 = 0; k0 < HID; k0 += 32) {
        float4 av = *reinterpret_cast<const float4*>(&A[(size_t)(m0 + arow) * HID + k0 + aq * 4]);
        As[arow][aq * 4 + 0] = av.x;
        As[arow][aq * 4 + 1] = av.y;
        As[arow][aq * 4 + 2] = av.z;
        As[arow][aq * 4 + 3] = av.w;
        Bs4[brow][bq]      = *reinterpret_cast<const float4*>(&W[(size_t)(k0 + brow) * HID + n0 + bq * 4]);
        Bs4[brow + 16][bq] = *reinterpret_cast<const float4*>(&W[(size_t)(k0 + brow + 16) * HID + n0 + bq * 4]);
        __syncthreads();
#pragma unroll
        for (int kk = 0; kk < 32; kk++) {
            float4 bb = Bs4[kk][tx];
            float a0 = As[ty * 2 + 0][kk];
            float a1 = As[ty * 2 + 1][kk];
            acc[0][0] += a0 * bb.x; acc[0][1] += a0 * bb.y; acc[0][2] += a0 * bb.z; acc[0][3] += a0 * bb.w;
            acc[1][0] += a1 * bb.x; acc[1][1] += a1 * bb.y; acc[1][2] += a1 * bb.z; acc[1][3] += a1 * bb.w;
        }
        __syncthreads();
    }

    float4 bv = *reinterpret_cast<const float4*>(&bias[n0 + tx * 4]);
    float v0[4], v1[4];
    v0[0] = acc[0][0] + bv.x; v0[1] = acc[0][1] + bv.y; v0[2] = acc[0][2] + bv.z; v0[3] = acc[0][3] + bv.w;
    v1[0] = acc[1][0] + bv.x; v1[1] = acc[1][1] + bv.y; v1[2] = acc[1][2] + bv.z; v1[3] = acc[1][3] + bv.w;

    float4 o0 = make_float4(v0[0], v0[1], v0[2], v0[3]);
    float4 o1 = make_float4(v1[0], v1[1], v1[2], v1[3]);
    *reinterpret_cast<float4*>(&C[(size_t)(m0 + ty * 2 + 0) * HID + n0 + tx * 4]) = o0;
    *reinterpret_cast<float4*>(&C[(size_t)(m0 + ty * 2 + 1) * HID + n0 + tx * 4]) = o1;

#pragma unroll
    for (int j = 0; j < 4; j++) {
        red_s[ty][tx * 4 + j] = v0[j] + v1[j];
        red_q[ty][tx * 4 + j] = v0[j] * v0[j] + v1[j] * v1[j];
    }
    __syncthreads();
    if (t < 64) {
        float S = 0.f, Q = 0.f;
#pragma unroll
        for (int g = 0; g < 16; g++) { S += red_s[g][t]; Q += red_q[g][t]; }
        atomicAdd(&gsum[n0 + t],   S);
        atomicAdd(&gsumsq[n0 + t], Q);
    }
}

// ---------------------------------------------------------------------------
// 3) GEMM2: vn = relu(h1*scale + shift) @ W2 + b2.
//    Prologue computes scale/shift per channel from gsum/gsumsq in smem.
// ---------------------------------------------------------------------------
__global__ __launch_bounds__(256) void gemm2_kernel(
    const float* __restrict__ A, const float* __restrict__ W,
    const float* __restrict__ bias, const float* __restrict__ gamma,
    const float* __restrict__ beta, const float* __restrict__ gsum,
    const float* __restrict__ gsumsq, float* __restrict__ C)
{
    __shared__ float  As[32][33];
    __shared__ float4 Bs4[32][16];
    __shared__ float  scale_s[HID];
    __shared__ float  shift_s[HID];

    int t  = threadIdx.x;
    {
        float mean = gsum[t] * (1.f / NB);
        float var  = gsumsq[t] * (1.f / NB) - mean * mean;
        float sc   = gamma[t] * rsqrtf(var + EPS);
        scale_s[t] = sc;
        shift_s[t] = beta[t] - mean * sc;
    }
    __syncthreads();

    int tx = t & 15, ty = t >> 4;
    int m0 = blockIdx.y * 32;
    int n0 = blockIdx.x * 64;

    float acc[2][4];
#pragma unroll
    for (int i = 0; i < 2; i++)
#pragma unroll
        for (int j = 0; j < 4; j++) acc[i][j] = 0.f;

    int arow = t >> 3, aq = t & 7;
    int brow = t >> 4, bq = t & 15;

    for (int k0 = 0; k0 < HID; k0 += 32) {
        int kc = k0 + aq * 4;
        float4 av = *reinterpret_cast<const float4*>(&A[(size_t)(m0 + arow) * HID + kc]);
        As[arow][aq * 4 + 0] = fmaxf(av.x * scale_s[kc + 0] + shift_s[kc + 0], 0.f);
        As[arow][aq * 4 + 1] = fmaxf(av.y * scale_s[kc + 1] + shift_s[kc + 1], 0.f);
        As[arow][aq * 4 + 2] = fmaxf(av.z * scale_s[kc + 2] + shift_s[kc + 2], 0.f);
        As[arow][aq * 4 + 3] = fmaxf(av.w * scale_s[kc + 3] + shift_s[kc + 3], 0.f);
        Bs4[brow][bq]      = *reinterpret_cast<const float4*>(&W[(size_t)(k0 + brow) * HID + n0 + bq * 4]);
        Bs4[brow + 16][bq] = *reinterpret_cast<const float4*>(&W[(size_t)(k0 + brow + 16) * HID + n0 + bq * 4]);
        __syncthreads();
#pragma unroll
        for (int kk = 0; kk < 32; kk++) {
            float4 bb = Bs4[kk][tx];
            float a0 = As[ty * 2 + 0][kk];
            float a1 = As[ty * 2 + 1][kk];
            acc[0][0] += a0 * bb.x; acc[0][1] += a0 * bb.y; acc[0][2] += a0 * bb.z; acc[0][3] += a0 * bb.w;
            acc[1][0] += a1 * bb.x; acc[1][1] += a1 * bb.y; acc[1][2] += a1 * bb.z; acc[1][3] += a1 * bb.w;
        }
        __syncthreads();
    }

    float4 bv = *reinterpret_cast<const float4*>(&bias[n0 + tx * 4]);
#pragma unroll
    for (int i = 0; i < 2; i++) {
        float4 o;
        o.x = acc[i][0] + bv.x; o.y = acc[i][1] + bv.y;
        o.z = acc[i][2] + bv.z; o.w = acc[i][3] + bv.w;
        *reinterpret_cast<float4*>(&C[(size_t)(m0 + ty * 2 + i) * HID + n0 + tx * 4]) = o;
    }
}

// ---------------------------------------------------------------------------
// 4) gather broadcast-add: x_out = x + vn[batch_idx].
//    4 independent float4 per thread (MLP=4+), all loads front-batched.
//    x streamed (ldcs), out streamed (stcs); vn/bidx stay L2-resident.
// ---------------------------------------------------------------------------
__global__ __launch_bounds__(256) void gather_kernel(
    const float* __restrict__ x, const int* __restrict__ bidx,
    const float* __restrict__ vn, float* __restrict__ out, long total4)
{
    const float4* x4  = reinterpret_cast<const float4*>(x);
    const float4* vn4 = reinterpret_cast<const float4*>(vn);
    float4*       o4  = reinterpret_cast<float4*>(out);

    long base = (long)blockIdx.x * 1024 + threadIdx.x;

    long idx[4];
    bool ok[4];
    int  g[4];
#pragma unroll
    for (int j = 0; j < 4; j++) {
        idx[j] = base + j * 256;
        ok[j]  = idx[j] < total4;
    }
    // front-batch the index loads
#pragma unroll
    for (int j = 0; j < 4; j++)
        g[j] = ok[j] ? __ldg(&bidx[(int)(idx[j] >> 6)]) : 0;

    // front-batch the x loads (streaming)
    float4 a[4];
#pragma unroll
    for (int j = 0; j < 4; j++)
        if (ok[j]) a[j] = __ldcs(&x4[idx[j]]);

    // vn loads (L2-resident)
    float4 v[4];
#pragma unroll
    for (int j = 0; j < 4; j++)
        if (ok[j]) v[j] = vn4[(size_t)g[j] * H4 + (idx[j] & 63)];

#pragma unroll
    for (int j = 0; j < 4; j++) {
        if (ok[j]) {
            float4 o;
            o.x = a[j].x + v[j].x; o.y = a[j].y + v[j].y;
            o.z = a[j].z + v[j].z; o.w = a[j].w + v[j].w;
            __stcs(&o4[idx[j]], o);
        }
    }
}

// ---------------------------------------------------------------------------
extern "C" void kernel_launch(void* const* d_in, const int* in_sizes, int n_in,
                              void* d_out, int out_size)
{
    const float* x     = (const float*)d_in[0];
    const int*   bidx  = (const int*)  d_in[1];
    const float* vnode = (const float*)d_in[2];
    const float* W1    = (const float*)d_in[3];
    const float* b1    = (const float*)d_in[4];
    const float* gamma = (const float*)d_in[5];
    const float* beta  = (const float*)d_in[6];
    const float* W2    = (const float*)d_in[7];
    const float* b2    = (const float*)d_in[8];

    int n = in_sizes[0] / HID;             // number of nodes

    float* out   = (float*)d_out;          // x_out: [n, H]
    float* vnout = out + (size_t)n * HID;  // vn: [B, H]

    float* hpool; cudaGetSymbolAddress((void**)&hpool, g_hpool);
    float* h1;    cudaGetSymbolAddress((void**)&h1,    g_h1);
    float* gsum;  cudaGetSymbolAddress((void**)&gsum,  g_sum);
    float* gsq;   cudaGetSymbolAddress((void**)&gsq,   g_sumsq);

    pool_kernel<<<NB * 2, 256>>>(x, bidx, vnode, hpool, gsum, gsq, n);

    dim3 ggrid(HID / 64, NB / 32);         // (4, 32) = 128 blocks
    gemm1_kernel<<<ggrid, 256>>>(hpool, W1, b1, h1, gsum, gsq);
    gemm2_kernel<<<ggrid, 256>>>(h1, W2, b2, gamma, beta, gsum, gsq, vnout);

    long total4 = (long)n * H4;
    int blocks = (int)((total4 + 1023) / 1024);
    gather_kernel<<<blocks, 256>>>(x, bidx, vnout, out, total4);
}